// round 13
// baseline (speedup 1.0000x reference)
#include <cuda_runtime.h>
#include <cuda_fp16.h>
#include <mma.h>
#include <cstdint>

using namespace nvcuda;

// ---------------- problem-size constants (padded maxima for static scratch) ---
constexpr int NMAX = 50048;        // >= 50000 nodes
constexpr int SCAN_BLOCKS = 52;
constexpr int NPAD = SCAN_BLOCKS * 1024;   // 53248 (scan coverage)
constexpr int EMAX = 1600000;      // edges
constexpr int HID  = 128;          // hidden width (both layers use 128 cols)

// ---------------- static device scratch (no allocations allowed) -------------
// g_deg tail [NPAD, NPAD+64) doubles as scan block-sum flags (memset covers it)
__device__ int    g_deg[NPAD + 64];
__device__ float  g_dinv[NPAD];
__device__ int    g_rowstart[NPAD + 4];
__device__ int    g_rank[EMAX];
__device__ int    g_csr_src[EMAX];
__device__ __half g_Hs1[(size_t)NMAX * HID];  // x@W1, then prescaled by dinv (fp16)
__device__ __half g_hh[(size_t)NMAX * HID];   // hs = dinv*relu(...) fp16 (layer-2 gather)
__device__ __half g_P2[(size_t)NMAX * HID];   // aggregated hs (GEMM2 A input), fp16

// ---------------- CSR build ---------------------------------------------------
// 4 edges per thread: independent atomic chains for MLP
__global__ void k_hist_rank4(const int* __restrict__ dst, int E) {
    int i = blockIdx.x * blockDim.x + threadIdx.x;
    int base = i * 4;
    if (base + 4 <= E) {
        int4 d = *(const int4*)&dst[base];
        int r0 = atomicAdd(&g_deg[d.x], 1);
        int r1 = atomicAdd(&g_deg[d.y], 1);
        int r2 = atomicAdd(&g_deg[d.z], 1);
        int r3 = atomicAdd(&g_deg[d.w], 1);
        *(int4*)&g_rank[base] = make_int4(r0, r1, r2, r3);
    } else {
        for (int j = base; j < E; j++) g_rank[j] = atomicAdd(&g_deg[dst[j]], 1);
    }
}

// grid-wide exclusive scan, single pass: 52 blocks x 1024 threads, 1 elem/thread.
// Each block publishes (block_total + 1) into g_deg[NPAD + b]; threads t < b poll
// the earlier flags concurrently and block-reduce the prefix offset. All 52
// blocks are co-resident (52 << 148 SMs), so polling cannot deadlock.
__global__ __launch_bounds__(1024) void k_scan2() {
    __shared__ int sh_scan[32];
    __shared__ int sh_red[32];
    __shared__ int s_total, s_off;
    const int b = blockIdx.x, t = threadIdx.x;
    const int idx = b * 1024 + t;
    const int d = g_deg[idx];
    const int lane = t & 31, wid = t >> 5;

    int v = d;
    #pragma unroll
    for (int s = 1; s < 32; s <<= 1) {
        int n = __shfl_up_sync(0xffffffff, v, s);
        if (lane >= s) v += n;
    }
    if (lane == 31) sh_scan[wid] = v;
    __syncthreads();
    if (wid == 0) {
        int w = sh_scan[lane];
        #pragma unroll
        for (int s = 1; s < 32; s <<= 1) {
            int n = __shfl_up_sync(0xffffffff, w, s);
            if (lane >= s) w += n;
        }
        sh_scan[lane] = w;
    }
    __syncthreads();
    int incl = v + (wid > 0 ? sh_scan[wid - 1] : 0);
    int excl = incl - d;
    if (t == 1023) s_total = incl;
    __syncthreads();

    if (t == 0) {
        __threadfence();
        atomicExch(&g_deg[NPAD + b], s_total + 1);
    }

    int p = 0;
    if (t < b) {
        int vv;
        while ((vv = atomicAdd(&g_deg[NPAD + t], 0)) == 0) { __nanosleep(50); }
        p = vv - 1;
    }
    #pragma unroll
    for (int s = 16; s > 0; s >>= 1) p += __shfl_down_sync(0xffffffff, p, s);
    if (lane == 0) sh_red[wid] = p;
    __syncthreads();
    if (wid == 0) {
        int w = sh_red[lane];
        #pragma unroll
        for (int s = 16; s > 0; s >>= 1) w += __shfl_down_sync(0xffffffff, w, s);
        if (lane == 0) s_off = w;
    }
    __syncthreads();

    g_rowstart[idx] = excl + s_off;
    g_dinv[idx] = rsqrtf((float)(d + 1));   // +1 self-loop (pad rows -> 1, unused)
}

// 4 edges per thread: 4 independent load->load->store chains
__global__ void k_scatter4(const int* __restrict__ src, const int* __restrict__ dst, int E) {
    int i = blockIdx.x * blockDim.x + threadIdx.x;
    int base = i * 4;
    if (base + 4 <= E) {
        int4 d = *(const int4*)&dst[base];
        int4 r = *(const int4*)&g_rank[base];
        int4 s = *(const int4*)&src[base];
        int p0 = g_rowstart[d.x] + r.x;
        int p1 = g_rowstart[d.y] + r.y;
        int p2 = g_rowstart[d.z] + r.z;
        int p3 = g_rowstart[d.w] + r.w;
        g_csr_src[p0] = s.x;
        g_csr_src[p1] = s.y;
        g_csr_src[p2] = s.z;
        g_csr_src[p3] = s.w;
    } else {
        for (int j = base; j < E; j++)
            g_csr_src[g_rowstart[dst[j]] + g_rank[j]] = src[j];
    }
}

// in-place row prescale: Hs1[r,:] *= dinv[r]  (uint2 = 4 halves per thread)
__global__ void k_prescale(int total) {
    int i = blockIdx.x * blockDim.x + threadIdx.x;
    if (i >= total) return;
    int row = i >> 5;                         // warp-uniform
    float w = g_dinv[row];
    uint2 u = ((const uint2*)g_Hs1)[i];
    float2 lo = __half22float2(*reinterpret_cast<__half2*>(&u.x));
    float2 hi = __half22float2(*reinterpret_cast<__half2*>(&u.y));
    __half2 h0 = __float22half2_rn(make_float2(lo.x * w, lo.y * w));
    __half2 h1 = __float22half2_rn(make_float2(hi.x * w, hi.y * w));
    uint2 o;
    o.x = *reinterpret_cast<unsigned*>(&h0);
    o.y = *reinterpret_cast<unsigned*>(&h1);
    ((uint2*)g_Hs1)[i] = o;
}

// ---------------- helpers ------------------------------------------------------
__device__ __forceinline__ void acc_h4(float4& a, uint2 u) {
    float2 lo = __half22float2(*reinterpret_cast<__half2*>(&u.x));
    float2 hi = __half22float2(*reinterpret_cast<__half2*>(&u.y));
    a.x += lo.x; a.y += lo.y; a.z += hi.x; a.w += hi.y;
}

// unweighted gather-sum (rows already dinv-prescaled); MLP-8 main loop
__device__ __forceinline__ float4 gather_sum(const uint2* __restrict__ Hs4,
                                             int node, int lane) {
    uint2 self = Hs4[(size_t)node * 32 + lane];
    float4 acc = make_float4(0.f, 0.f, 0.f, 0.f);
    acc_h4(acc, self);

    int e = g_rowstart[node];
    const int end = g_rowstart[node + 1];
    for (; e + 8 <= end; e += 8) {
        int s0 = g_csr_src[e + 0], s1 = g_csr_src[e + 1];
        int s2 = g_csr_src[e + 2], s3 = g_csr_src[e + 3];
        int s4 = g_csr_src[e + 4], s5 = g_csr_src[e + 5];
        int s6 = g_csr_src[e + 6], s7 = g_csr_src[e + 7];
        uint2 u0 = __ldg(&Hs4[(size_t)s0 * 32 + lane]);
        uint2 u1 = __ldg(&Hs4[(size_t)s1 * 32 + lane]);
        uint2 u2 = __ldg(&Hs4[(size_t)s2 * 32 + lane]);
        uint2 u3 = __ldg(&Hs4[(size_t)s3 * 32 + lane]);
        uint2 u4 = __ldg(&Hs4[(size_t)s4 * 32 + lane]);
        uint2 u5 = __ldg(&Hs4[(size_t)s5 * 32 + lane]);
        uint2 u6 = __ldg(&Hs4[(size_t)s6 * 32 + lane]);
        uint2 u7 = __ldg(&Hs4[(size_t)s7 * 32 + lane]);
        acc_h4(acc, u0); acc_h4(acc, u1); acc_h4(acc, u2); acc_h4(acc, u3);
        acc_h4(acc, u4); acc_h4(acc, u5); acc_h4(acc, u6); acc_h4(acc, u7);
    }
    for (; e + 2 <= end; e += 2) {
        int s0 = g_csr_src[e + 0], s1 = g_csr_src[e + 1];
        uint2 u0 = __ldg(&Hs4[(size_t)s0 * 32 + lane]);
        uint2 u1 = __ldg(&Hs4[(size_t)s1 * 32 + lane]);
        acc_h4(acc, u0); acc_h4(acc, u1);
    }
    if (e < end) {
        uint2 u = __ldg(&Hs4[(size_t)g_csr_src[e] * 32 + lane]);
        acc_h4(acc, u);
    }
    return acc;
}

// ---------------- aggregation, one warp per node -------------------------------
// layer 1: P1 = dinv[d]*(gather of prescaled Hs1); h = relu(P1 + b1)
// writes hs = dinv[d]*h (fp16) so layer-2 gather needs no weights
__global__ __launch_bounds__(256) void k_agg_relu(int N, const float* __restrict__ b) {
    int warp = (blockIdx.x * blockDim.x + threadIdx.x) >> 5;
    int lane = threadIdx.x & 31;
    if (warp >= N) return;
    float4 acc = gather_sum((const uint2*)g_Hs1, warp, lane);

    float dd = g_dinv[warp];
    int c = lane * 4;
    float4 bb = *(const float4*)&b[c];
    float hx = fmaxf(acc.x * dd + bb.x, 0.f) * dd;
    float hy = fmaxf(acc.y * dd + bb.y, 0.f) * dd;
    float hz = fmaxf(acc.z * dd + bb.z, 0.f) * dd;
    float hw = fmaxf(acc.w * dd + bb.w, 0.f) * dd;
    __half2 h0 = __float22half2_rn(make_float2(hx, hy));
    __half2 h1 = __float22half2_rn(make_float2(hz, hw));
    uint2 pack;
    pack.x = *reinterpret_cast<unsigned*>(&h0);
    pack.y = *reinterpret_cast<unsigned*>(&h1);
    ((uint2*)g_hh)[(size_t)warp * 32 + lane] = pack;
}

// layer 2 aggregation (commuted before GEMM2): P2[d] = dinv[d]*(hs[d] + sum hs[s])
__global__ __launch_bounds__(256) void k_agg2(int N) {
    int warp = (blockIdx.x * blockDim.x + threadIdx.x) >> 5;
    int lane = threadIdx.x & 31;
    if (warp >= N) return;
    float4 acc = gather_sum((const uint2*)g_hh, warp, lane);

    float dd = g_dinv[warp];
    __half2 h0 = __float22half2_rn(make_float2(acc.x * dd, acc.y * dd));
    __half2 h1 = __float22half2_rn(make_float2(acc.z * dd, acc.w * dd));
    uint2 pack;
    pack.x = *reinterpret_cast<unsigned*>(&h0);
    pack.y = *reinterpret_cast<unsigned*>(&h1);
    ((uint2*)g_P2)[(size_t)warp * 32 + lane] = pack;
}

// ---------------- tensor-core GEMM1: Hs1[M,128] = fp16(x[M,256] @ W1) ----------
// A fp32 converted on load; B fp32 (W1) converted on load. BM=128,BN=128,BK=32.
__global__ __launch_bounds__(256) void k_hgemm1(int M, int K,
                                                const float* __restrict__ A,
                                                const float* __restrict__ B,
                                                __half* __restrict__ Hs) {
    constexpr int BM = 128, BN = 128, BK = 32;
    __shared__ __align__(32) __half As[BM][BK + 8];
    __shared__ __align__(32) __half Bs[BK][BN + 8];
    __shared__ __align__(32) float  Cs[8][16][24];

    const int tid = threadIdx.x;
    const int wid = tid >> 5;
    const int lane = tid & 31;
    const int warp_m = wid >> 1;
    const int warp_n = wid & 1;
    const int block_row = blockIdx.x * BM;

    wmma::fragment<wmma::accumulator, 16, 16, 16, float> facc[2][4];
    #pragma unroll
    for (int i = 0; i < 2; i++)
        #pragma unroll
        for (int j = 0; j < 4; j++) wmma::fill_fragment(facc[i][j], 0.0f);

    for (int k0 = 0; k0 < K; k0 += BK) {
        #pragma unroll
        for (int i = 0; i < 4; i++) {
            int idx = tid + i * 256;
            int r = idx >> 3, c4 = (idx & 7) * 4;
            int gr = block_row + r;
            float4 v = make_float4(0.f, 0.f, 0.f, 0.f);
            if (gr < M) v = *(const float4*)&A[(size_t)gr * K + k0 + c4];
            __half2 h0 = __float22half2_rn(make_float2(v.x, v.y));
            __half2 h1 = __float22half2_rn(make_float2(v.z, v.w));
            uint2 pack;
            pack.x = *reinterpret_cast<unsigned*>(&h0);
            pack.y = *reinterpret_cast<unsigned*>(&h1);
            *(uint2*)&As[r][c4] = pack;
        }
        #pragma unroll
        for (int i = 0; i < 4; i++) {
            int idx = tid + i * 256;
            int r = idx >> 5, c4 = (idx & 31) * 4;
            float4 v = *(const float4*)&B[(size_t)(k0 + r) * BN + c4];
            __half2 h0 = __float22half2_rn(make_float2(v.x, v.y));
            __half2 h1 = __float22half2_rn(make_float2(v.z, v.w));
            uint2 pack;
            pack.x = *reinterpret_cast<unsigned*>(&h0);
            pack.y = *reinterpret_cast<unsigned*>(&h1);
            *(uint2*)&Bs[r][c4] = pack;
        }
        __syncthreads();

        #pragma unroll
        for (int kk = 0; kk < BK; kk += 16) {
            wmma::fragment<wmma::matrix_a, 16, 16, 16, __half, wmma::row_major> fa[2];
            wmma::fragment<wmma::matrix_b, 16, 16, 16, __half, wmma::row_major> fb[4];
            #pragma unroll
            for (int i = 0; i < 2; i++)
                wmma::load_matrix_sync(fa[i], &As[warp_m * 32 + i * 16][kk], BK + 8);
            #pragma unroll
            for (int j = 0; j < 4; j++)
                wmma::load_matrix_sync(fb[j], &Bs[kk][warp_n * 64 + j * 16], BN + 8);
            #pragma unroll
            for (int i = 0; i < 2; i++)
                #pragma unroll
                for (int j = 0; j < 4; j++)
                    wmma::mma_sync(facc[i][j], fa[i], fb[j], facc[i][j]);
        }
        __syncthreads();
    }

    #pragma unroll
    for (int i = 0; i < 2; i++) {
        #pragma unroll
        for (int j = 0; j < 4; j++) {
            wmma::store_matrix_sync(&Cs[wid][0][0], facc[i][j], 24, wmma::mem_row_major);
            __syncwarp();
            int r = lane >> 1;
            int gr = block_row + warp_m * 32 + i * 16 + r;
            int col = warp_n * 64 + j * 16 + (lane & 1) * 8;
            if (gr < M) {
                float4 v0 = *(float4*)&Cs[wid][r][(lane & 1) * 8];
                float4 v1 = *(float4*)&Cs[wid][r][(lane & 1) * 8 + 4];
                __half2 h0 = __float22half2_rn(make_float2(v0.x, v0.y));
                __half2 h1 = __float22half2_rn(make_float2(v0.z, v0.w));
                __half2 h2 = __float22half2_rn(make_float2(v1.x, v1.y));
                __half2 h3 = __float22half2_rn(make_float2(v1.z, v1.w));
                uint4 pack;
                pack.x = *reinterpret_cast<unsigned*>(&h0);
                pack.y = *reinterpret_cast<unsigned*>(&h1);
                pack.z = *reinterpret_cast<unsigned*>(&h2);
                pack.w = *reinterpret_cast<unsigned*>(&h3);
                *(uint4*)&Hs[(size_t)gr * BN + col] = pack;
            }
            __syncwarp();
        }
    }
}

// ---------------- GEMM2 -> output: out = split(P2 @ [Wmu|Wls]) + bias ---------
// A = P2 fp16 [M,128]; B built on the fly from Wmu/Wls fp32; C fp32 direct to out.
__global__ __launch_bounds__(256) void k_hgemm_out(int M, int Nn,
                                                   const __half* __restrict__ A,
                                                   const float* __restrict__ Wmu,
                                                   const float* __restrict__ Wls,
                                                   const float* __restrict__ bmu,
                                                   const float* __restrict__ bls,
                                                   float* __restrict__ out) {
    constexpr int BM = 128, BN = 128, BK = 32, K = 128;
    __shared__ __align__(32) __half As[BM][BK + 8];
    __shared__ __align__(32) __half Bs[BK][BN + 8];
    __shared__ __align__(32) float  Cs[8][16][24];

    const int tid = threadIdx.x;
    const int wid = tid >> 5;
    const int lane = tid & 31;
    const int warp_m = wid >> 1;
    const int warp_n = wid & 1;
    const int block_row = blockIdx.x * BM;

    wmma::fragment<wmma::accumulator, 16, 16, 16, float> facc[2][4];
    #pragma unroll
    for (int i = 0; i < 2; i++)
        #pragma unroll
        for (int j = 0; j < 4; j++) wmma::fill_fragment(facc[i][j], 0.0f);

    for (int k0 = 0; k0 < K; k0 += BK) {
        #pragma unroll
        for (int i = 0; i < 4; i++) {
            int idx = tid + i * 256;
            int r = idx >> 3, c4 = (idx & 7) * 4;
            int gr = block_row + r;
            uint2 v = make_uint2(0u, 0u);
            if (gr < M) v = *(const uint2*)&A[(size_t)gr * K + k0 + c4];
            *(uint2*)&As[r][c4] = v;
        }
        #pragma unroll
        for (int i = 0; i < 4; i++) {
            int idx = tid + i * 256;
            int r = k0 + (idx >> 5), c4 = (idx & 31) * 4;   // c4: 0..124, mult of 4
            float4 v = (c4 < 64) ? *(const float4*)&Wmu[(size_t)r * 64 + c4]
                                 : *(const float4*)&Wls[(size_t)r * 64 + (c4 - 64)];
            __half2 h0 = __float22half2_rn(make_float2(v.x, v.y));
            __half2 h1 = __float22half2_rn(make_float2(v.z, v.w));
            uint2 pack;
            pack.x = *reinterpret_cast<unsigned*>(&h0);
            pack.y = *reinterpret_cast<unsigned*>(&h1);
            *(uint2*)&Bs[(idx >> 5)][c4] = pack;
        }
        __syncthreads();

        #pragma unroll
        for (int kk = 0; kk < BK; kk += 16) {
            wmma::fragment<wmma::matrix_a, 16, 16, 16, __half, wmma::row_major> fa[2];
            wmma::fragment<wmma::matrix_b, 16, 16, 16, __half, wmma::row_major> fb[4];
            #pragma unroll
            for (int i = 0; i < 2; i++)
                wmma::load_matrix_sync(fa[i], &As[warp_m * 32 + i * 16][kk], BK + 8);
            #pragma unroll
            for (int j = 0; j < 4; j++)
                wmma::load_matrix_sync(fb[j], &Bs[kk][warp_n * 64 + j * 16], BN + 8);
            #pragma unroll
            for (int i = 0; i < 2; i++)
                #pragma unroll
                for (int j = 0; j < 4; j++)
                    wmma::mma_sync(facc[i][j], fa[i], fb[j], facc[i][j]);
        }
        __syncthreads();
    }

    // epilogue: add bias, split mu/logstd halves, write fp32 to out
    #pragma unroll
    for (int i = 0; i < 2; i++) {
        #pragma unroll
        for (int j = 0; j < 4; j++) {
            wmma::store_matrix_sync(&Cs[wid][0][0], facc[i][j], 24, wmma::mem_row_major);
            __syncwarp();
            int r = lane >> 1;
            int gr = block_row + warp_m * 32 + i * 16 + r;
            int colg = warp_n * 64 + j * 16 + (lane & 1) * 8;   // 0..120
            if (gr < M) {
                float4 v0 = *(float4*)&Cs[wid][r][(lane & 1) * 8];
                float4 v1 = *(float4*)&Cs[wid][r][(lane & 1) * 8 + 4];
                if (colg < 64) {
                    float4 b0 = *(const float4*)&bmu[colg];
                    float4 b1 = *(const float4*)&bmu[colg + 4];
                    size_t base = (size_t)gr * 64 + colg;
                    *(float4*)&out[base]     = make_float4(v0.x + b0.x, v0.y + b0.y, v0.z + b0.z, v0.w + b0.w);
                    *(float4*)&out[base + 4] = make_float4(v1.x + b1.x, v1.y + b1.y, v1.z + b1.z, v1.w + b1.w);
                } else {
                    int c2 = colg - 64;
                    float4 b0 = *(const float4*)&bls[c2];
                    float4 b1 = *(const float4*)&bls[c2 + 4];
                    size_t base = (size_t)Nn * 64 + (size_t)gr * 64 + c2;
                    *(float4*)&out[base]     = make_float4(v0.x + b0.x, v0.y + b0.y, v0.z + b0.z, v0.w + b0.w);
                    *(float4*)&out[base + 4] = make_float4(v1.x + b1.x, v1.y + b1.y, v1.z + b1.z, v1.w + b1.w);
                }
            }
            __syncwarp();
        }
    }
}

// ---------------- launch ------------------------------------------------------
extern "C" void kernel_launch(void* const* d_in, const int* in_sizes, int n_in,
                              void* d_out, int out_size) {
    const float* x  = (const float*)d_in[0];
    const int*   ei = (const int*)d_in[1];
    int base = (n_in >= 9 && in_sizes[2] == 1) ? 3 : 2;
    const float* W1  = (const float*)d_in[base + 0];
    const float* b1  = (const float*)d_in[base + 1];
    const float* Wmu = (const float*)d_in[base + 2];
    const float* bmu = (const float*)d_in[base + 3];
    const float* Wls = (const float*)d_in[base + 4];
    const float* bls = (const float*)d_in[base + 5];
    float* out = (float*)d_out;

    const int N = in_sizes[0] / 256;   // 50000
    const int E = in_sizes[1] / 2;     // 1600000
    const int* src = ei;
    const int* dst = ei + E;

    __half *pHs1, *pP2;
    int* pdeg;
    cudaGetSymbolAddress((void**)&pHs1, g_Hs1);
    cudaGetSymbolAddress((void**)&pP2,  g_P2);
    cudaGetSymbolAddress((void**)&pdeg, g_deg);

    // one-time side-stream + events (host resources, not device memory)
    static cudaStream_t s2 = nullptr;
    static cudaEvent_t ev0 = nullptr, ev_scan = nullptr, ev_pre = nullptr;
    if (!s2) {
        cudaStreamCreateWithFlags(&s2, cudaStreamNonBlocking);
        cudaEventCreateWithFlags(&ev0, cudaEventDisableTiming);
        cudaEventCreateWithFlags(&ev_scan, cudaEventDisableTiming);
        cudaEventCreateWithFlags(&ev_pre, cudaEventDisableTiming);
    }

    const int T = 256;
    // ---- fork at t=0: s2 runs GEMM1 (graph-independent, weights converted inline)
    cudaEventRecord(ev0, 0);
    cudaStreamWaitEvent(s2, ev0, 0);
    k_hgemm1<<<(N + 127) / 128, 256, 0, s2>>>(N, 256, x, W1, pHs1);

    // ---- main stream: CSR build chain (memset covers scan pad + flags) ----
    cudaMemsetAsync(pdeg, 0, (size_t)(NPAD + 64) * sizeof(int), 0);
    k_hist_rank4<<<(E / 4 + T - 1) / T + 1, T>>>(dst, E);
    k_scan2<<<SCAN_BLOCKS, 1024>>>();
    cudaEventRecord(ev_scan, 0);
    k_scatter4<<<(E / 4 + T - 1) / T + 1, T>>>(src, dst, E);

    // ---- s2: prescale Hs1 by dinv (after GEMM1 + scan), overlaps scatter ----
    cudaStreamWaitEvent(s2, ev_scan, 0);
    k_prescale<<<(N * 32 + T - 1) / T, T, 0, s2>>>(N * 32);
    cudaEventRecord(ev_pre, s2);

    // ---- join, then the serial tail: agg1 -> agg2 -> GEMM2(out) ----
    cudaStreamWaitEvent(0, ev_pre, 0);
    k_agg_relu<<<(N * 32 + T - 1) / T, T>>>(N, b1);
    k_agg2<<<(N * 32 + T - 1) / T, T>>>(N);
    k_hgemm_out<<<(N + 127) / 128, 256>>>(N, N, pP2, Wmu, Wls, bmu, bls, out);
}

// round 14
// speedup vs baseline: 1.5775x; 1.5775x over previous
#include <cuda_runtime.h>
#include <cuda_fp16.h>
#include <mma.h>
#include <cstdint>

using namespace nvcuda;

// ---------------- problem-size constants (padded maxima for static scratch) ---
constexpr int NMAX = 50048;        // >= 50000 nodes
constexpr int SCAN_BLOCKS = 52;
constexpr int NPAD = SCAN_BLOCKS * 1024;   // 53248 (scan coverage)
constexpr int EMAX = 1600000;      // edges
constexpr int HID  = 128;          // hidden width (both layers use 128 cols)

// ---------------- static device scratch (no allocations allowed) -------------
// g_deg tail [NPAD, NPAD+64) doubles as scan block-sum flags (memset covers it)
__device__ int    g_deg[NPAD + 64];
__device__ float  g_dinv[NPAD];
__device__ int    g_rowstart[NPAD + 4];
__device__ int    g_rank[EMAX];
__device__ int    g_csr_src[EMAX];
__device__ __half g_Hs1[(size_t)NMAX * HID];  // x@W1, then prescaled by dinv (fp16)
__device__ __half g_hh[(size_t)NMAX * HID];   // hidden activations fp16 (GEMM2 A)
__device__ __half g_Hs2[(size_t)NMAX * HID];  // dinv-scaled h@[Wmu|Wls], fp16
__device__ __half g_W1h[256 * HID];           // W1 fp16
__device__ __half g_W2h[HID * HID];           // concat(W_mu, W_ls) fp16

// ---------------- CSR build ---------------------------------------------------
// 8 edges per thread: 8 independent atomic chains for MLP
__global__ void k_hist_rank8(const int* __restrict__ dst, int E) {
    int i = blockIdx.x * blockDim.x + threadIdx.x;
    int base = i * 8;
    if (base + 8 <= E) {
        int4 da = *(const int4*)&dst[base];
        int4 db = *(const int4*)&dst[base + 4];
        int r0 = atomicAdd(&g_deg[da.x], 1);
        int r1 = atomicAdd(&g_deg[da.y], 1);
        int r2 = atomicAdd(&g_deg[da.z], 1);
        int r3 = atomicAdd(&g_deg[da.w], 1);
        int r4 = atomicAdd(&g_deg[db.x], 1);
        int r5 = atomicAdd(&g_deg[db.y], 1);
        int r6 = atomicAdd(&g_deg[db.z], 1);
        int r7 = atomicAdd(&g_deg[db.w], 1);
        *(int4*)&g_rank[base]     = make_int4(r0, r1, r2, r3);
        *(int4*)&g_rank[base + 4] = make_int4(r4, r5, r6, r7);
    } else {
        for (int j = base; j < E; j++) g_rank[j] = atomicAdd(&g_deg[dst[j]], 1);
    }
}

// grid-wide exclusive scan, single pass: 52 blocks x 1024 threads, 1 elem/thread.
// Each block publishes (block_total + 1) into g_deg[NPAD + b]; threads t < b poll
// the earlier flags concurrently and block-reduce the prefix offset. All 52
// blocks are co-resident (52 << 148 SMs), so polling cannot deadlock.
__global__ __launch_bounds__(1024) void k_scan2() {
    __shared__ int sh_scan[32];
    __shared__ int sh_red[32];
    __shared__ int s_total, s_off;
    const int b = blockIdx.x, t = threadIdx.x;
    const int idx = b * 1024 + t;
    const int d = g_deg[idx];
    const int lane = t & 31, wid = t >> 5;

    int v = d;
    #pragma unroll
    for (int s = 1; s < 32; s <<= 1) {
        int n = __shfl_up_sync(0xffffffff, v, s);
        if (lane >= s) v += n;
    }
    if (lane == 31) sh_scan[wid] = v;
    __syncthreads();
    if (wid == 0) {
        int w = sh_scan[lane];
        #pragma unroll
        for (int s = 1; s < 32; s <<= 1) {
            int n = __shfl_up_sync(0xffffffff, w, s);
            if (lane >= s) w += n;
        }
        sh_scan[lane] = w;
    }
    __syncthreads();
    int incl = v + (wid > 0 ? sh_scan[wid - 1] : 0);
    int excl = incl - d;
    if (t == 1023) s_total = incl;
    __syncthreads();

    if (t == 0) {
        __threadfence();
        atomicExch(&g_deg[NPAD + b], s_total + 1);
    }

    int p = 0;
    if (t < b) {
        int vv;
        while ((vv = atomicAdd(&g_deg[NPAD + t], 0)) == 0) { __nanosleep(50); }
        p = vv - 1;
    }
    #pragma unroll
    for (int s = 16; s > 0; s >>= 1) p += __shfl_down_sync(0xffffffff, p, s);
    if (lane == 0) sh_red[wid] = p;
    __syncthreads();
    if (wid == 0) {
        int w = sh_red[lane];
        #pragma unroll
        for (int s = 16; s > 0; s >>= 1) w += __shfl_down_sync(0xffffffff, w, s);
        if (lane == 0) s_off = w;
    }
    __syncthreads();

    g_rowstart[idx] = excl + s_off;
    g_dinv[idx] = rsqrtf((float)(d + 1));   // +1 self-loop (pad rows -> 1, unused)
}

// 8 edges per thread: 8 independent load->load->store chains
__global__ void k_scatter8(const int* __restrict__ src, const int* __restrict__ dst, int E) {
    int i = blockIdx.x * blockDim.x + threadIdx.x;
    int base = i * 8;
    if (base + 8 <= E) {
        int4 da = *(const int4*)&dst[base];
        int4 db = *(const int4*)&dst[base + 4];
        int4 ra = *(const int4*)&g_rank[base];
        int4 rb = *(const int4*)&g_rank[base + 4];
        int4 sa = *(const int4*)&src[base];
        int4 sb = *(const int4*)&src[base + 4];
        int p0 = g_rowstart[da.x] + ra.x;
        int p1 = g_rowstart[da.y] + ra.y;
        int p2 = g_rowstart[da.z] + ra.z;
        int p3 = g_rowstart[da.w] + ra.w;
        int p4 = g_rowstart[db.x] + rb.x;
        int p5 = g_rowstart[db.y] + rb.y;
        int p6 = g_rowstart[db.z] + rb.z;
        int p7 = g_rowstart[db.w] + rb.w;
        g_csr_src[p0] = sa.x;
        g_csr_src[p1] = sa.y;
        g_csr_src[p2] = sa.z;
        g_csr_src[p3] = sa.w;
        g_csr_src[p4] = sb.x;
        g_csr_src[p5] = sb.y;
        g_csr_src[p6] = sb.z;
        g_csr_src[p7] = sb.w;
    } else {
        for (int j = base; j < E; j++)
            g_csr_src[g_rowstart[dst[j]] + g_rank[j]] = src[j];
    }
}

// fused weight conversion: W1 (256x128) and [Wmu|Wls] (128x128) to fp16
__global__ void k_w12h(const float* __restrict__ W1, const float* __restrict__ Wmu,
                       const float* __restrict__ Wls) {
    int i = blockIdx.x * blockDim.x + threadIdx.x;
    if (i < 256 * HID) {
        g_W1h[i] = __float2half_rn(W1[i]);
    } else if (i < 256 * HID + HID * HID) {
        int j = i - 256 * HID;
        int k = j >> 7, c = j & 127;
        g_W2h[j] = __float2half_rn((c < 64) ? Wmu[k * 64 + c] : Wls[k * 64 + (c - 64)]);
    }
}

// in-place row prescale: Hs1[r,:] *= dinv[r]  (uint2 = 4 halves per thread)
__global__ void k_prescale(int total) {
    int i = blockIdx.x * blockDim.x + threadIdx.x;
    if (i >= total) return;
    int row = i >> 5;                         // warp-uniform
    float w = g_dinv[row];
    uint2 u = ((const uint2*)g_Hs1)[i];
    float2 lo = __half22float2(*reinterpret_cast<__half2*>(&u.x));
    float2 hi = __half22float2(*reinterpret_cast<__half2*>(&u.y));
    __half2 h0 = __float22half2_rn(make_float2(lo.x * w, lo.y * w));
    __half2 h1 = __float22half2_rn(make_float2(hi.x * w, hi.y * w));
    uint2 o;
    o.x = *reinterpret_cast<unsigned*>(&h0);
    o.y = *reinterpret_cast<unsigned*>(&h1);
    ((uint2*)g_Hs1)[i] = o;
}

// ---------------- helpers ------------------------------------------------------
__device__ __forceinline__ void acc_h4(float4& a, uint2 u) {
    float2 lo = __half22float2(*reinterpret_cast<__half2*>(&u.x));
    float2 hi = __half22float2(*reinterpret_cast<__half2*>(&u.y));
    a.x += lo.x; a.y += lo.y; a.z += hi.x; a.w += hi.y;
}

// unweighted gather-sum (rows already dinv-prescaled); MLP-8 main loop
__device__ __forceinline__ float4 gather_sum(const uint2* __restrict__ Hs4,
                                             int node, int lane) {
    uint2 self = Hs4[(size_t)node * 32 + lane];
    float4 acc = make_float4(0.f, 0.f, 0.f, 0.f);
    acc_h4(acc, self);

    int e = g_rowstart[node];
    const int end = g_rowstart[node + 1];
    for (; e + 8 <= end; e += 8) {
        int s0 = g_csr_src[e + 0], s1 = g_csr_src[e + 1];
        int s2 = g_csr_src[e + 2], s3 = g_csr_src[e + 3];
        int s4 = g_csr_src[e + 4], s5 = g_csr_src[e + 5];
        int s6 = g_csr_src[e + 6], s7 = g_csr_src[e + 7];
        uint2 u0 = __ldg(&Hs4[(size_t)s0 * 32 + lane]);
        uint2 u1 = __ldg(&Hs4[(size_t)s1 * 32 + lane]);
        uint2 u2 = __ldg(&Hs4[(size_t)s2 * 32 + lane]);
        uint2 u3 = __ldg(&Hs4[(size_t)s3 * 32 + lane]);
        uint2 u4 = __ldg(&Hs4[(size_t)s4 * 32 + lane]);
        uint2 u5 = __ldg(&Hs4[(size_t)s5 * 32 + lane]);
        uint2 u6 = __ldg(&Hs4[(size_t)s6 * 32 + lane]);
        uint2 u7 = __ldg(&Hs4[(size_t)s7 * 32 + lane]);
        acc_h4(acc, u0); acc_h4(acc, u1); acc_h4(acc, u2); acc_h4(acc, u3);
        acc_h4(acc, u4); acc_h4(acc, u5); acc_h4(acc, u6); acc_h4(acc, u7);
    }
    for (; e + 2 <= end; e += 2) {
        int s0 = g_csr_src[e + 0], s1 = g_csr_src[e + 1];
        uint2 u0 = __ldg(&Hs4[(size_t)s0 * 32 + lane]);
        uint2 u1 = __ldg(&Hs4[(size_t)s1 * 32 + lane]);
        acc_h4(acc, u0); acc_h4(acc, u1);
    }
    if (e < end) {
        uint2 u = __ldg(&Hs4[(size_t)g_csr_src[e] * 32 + lane]);
        acc_h4(acc, u);
    }
    return acc;
}

// ---------------- aggregation, one warp per node -------------------------------
// P[d,:] = dinv[d] * ( Hs[d,:] + sum_{edges s->d} Hs[s,:] )   (Hs prescaled)
// layer 1 variant: h = relu(P + b1), write fp16 (feeds tensor-core GEMM2)
__global__ __launch_bounds__(256) void k_agg_relu(int N, const float* __restrict__ b) {
    int warp = (blockIdx.x * blockDim.x + threadIdx.x) >> 5;
    int lane = threadIdx.x & 31;
    if (warp >= N) return;
    float4 acc = gather_sum((const uint2*)g_Hs1, warp, lane);

    float dd = g_dinv[warp];
    int c = lane * 4;
    float4 bb = *(const float4*)&b[c];
    __half2 h0 = __float22half2_rn(make_float2(fmaxf(acc.x * dd + bb.x, 0.f),
                                               fmaxf(acc.y * dd + bb.y, 0.f)));
    __half2 h1 = __float22half2_rn(make_float2(fmaxf(acc.z * dd + bb.z, 0.f),
                                               fmaxf(acc.w * dd + bb.w, 0.f)));
    uint2 pack;
    pack.x = *reinterpret_cast<unsigned*>(&h0);
    pack.y = *reinterpret_cast<unsigned*>(&h1);
    ((uint2*)g_hh)[(size_t)warp * 32 + lane] = pack;
}

// layer 2 variant: split into (mu, logstd) halves with biases, write to output
__global__ __launch_bounds__(256) void k_agg_out(int N, const float* __restrict__ bmu,
                                                 const float* __restrict__ bls,
                                                 float* __restrict__ out) {
    int warp = (blockIdx.x * blockDim.x + threadIdx.x) >> 5;
    int lane = threadIdx.x & 31;
    if (warp >= N) return;
    float4 acc = gather_sum((const uint2*)g_Hs2, warp, lane);

    float dd = g_dinv[warp];
    int c = lane * 4;   // 0..124
    float4 r;
    if (c < 64) {
        float4 bb = *(const float4*)&bmu[c];
        r.x = acc.x * dd + bb.x; r.y = acc.y * dd + bb.y;
        r.z = acc.z * dd + bb.z; r.w = acc.w * dd + bb.w;
        *(float4*)&out[(size_t)warp * 64 + c] = r;
    } else {
        float4 bb = *(const float4*)&bls[c - 64];
        r.x = acc.x * dd + bb.x; r.y = acc.y * dd + bb.y;
        r.z = acc.z * dd + bb.z; r.w = acc.w * dd + bb.w;
        *(float4*)&out[(size_t)N * 64 + (size_t)warp * 64 + (c - 64)] = r;
    }
}

// ---------------- tensor-core GEMM: Hs[M,128] = fp16([dinv[m]*](A[M,K]@B[K,128]))
// BM=128, BN=128, BK=32. 256 threads = 8 warps in 4x2 grid; warp tile 32x64.
template<bool A_IS_HALF, bool SCALE_D>
__global__ __launch_bounds__(256) void k_hgemm(int M, int K,
                                               const void* __restrict__ Av,
                                               const __half* __restrict__ B,
                                               __half* __restrict__ Hs) {
    constexpr int BM = 128, BN = 128, BK = 32;
    __shared__ __align__(32) __half As[BM][BK + 8];
    __shared__ __align__(32) __half Bs[BK][BN + 8];
    __shared__ __align__(32) float  Cs[8][16][24];

    const int tid = threadIdx.x;
    const int wid = tid >> 5;
    const int lane = tid & 31;
    const int warp_m = wid >> 1;          // 0..3
    const int warp_n = wid & 1;           // 0..1
    const int block_row = blockIdx.x * BM;

    wmma::fragment<wmma::accumulator, 16, 16, 16, float> facc[2][4];
    #pragma unroll
    for (int i = 0; i < 2; i++)
        #pragma unroll
        for (int j = 0; j < 4; j++) wmma::fill_fragment(facc[i][j], 0.0f);

    for (int k0 = 0; k0 < K; k0 += BK) {
        if (A_IS_HALF) {
            const __half* A = (const __half*)Av;
            #pragma unroll
            for (int i = 0; i < 4; i++) {
                int idx = tid + i * 256;
                int r = idx >> 3, c4 = (idx & 7) * 4;
                int gr = block_row + r;
                uint2 v = make_uint2(0u, 0u);
                if (gr < M) v = *(const uint2*)&A[(size_t)gr * K + k0 + c4];
                *(uint2*)&As[r][c4] = v;
            }
        } else {
            const float* A = (const float*)Av;
            #pragma unroll
            for (int i = 0; i < 4; i++) {
                int idx = tid + i * 256;
                int r = idx >> 3, c4 = (idx & 7) * 4;
                int gr = block_row + r;
                float4 v = make_float4(0.f, 0.f, 0.f, 0.f);
                if (gr < M) v = *(const float4*)&A[(size_t)gr * K + k0 + c4];
                __half2 h0 = __float22half2_rn(make_float2(v.x, v.y));
                __half2 h1 = __float22half2_rn(make_float2(v.z, v.w));
                uint2 pack;
                pack.x = *reinterpret_cast<unsigned*>(&h0);
                pack.y = *reinterpret_cast<unsigned*>(&h1);
                *(uint2*)&As[r][c4] = pack;
            }
        }
        #pragma unroll
        for (int i = 0; i < 4; i++) {
            int idx = tid + i * 256;
            int r = idx >> 5, c4 = (idx & 31) * 4;
            *(uint2*)&Bs[r][c4] = *(const uint2*)&B[(size_t)(k0 + r) * BN + c4];
        }
        __syncthreads();

        #pragma unroll
        for (int kk = 0; kk < BK; kk += 16) {
            wmma::fragment<wmma::matrix_a, 16, 16, 16, __half, wmma::row_major> fa[2];
            wmma::fragment<wmma::matrix_b, 16, 16, 16, __half, wmma::row_major> fb[4];
            #pragma unroll
            for (int i = 0; i < 2; i++)
                wmma::load_matrix_sync(fa[i], &As[warp_m * 32 + i * 16][kk], BK + 8);
            #pragma unroll
            for (int j = 0; j < 4; j++)
                wmma::load_matrix_sync(fb[j], &Bs[kk][warp_n * 64 + j * 16], BN + 8);
            #pragma unroll
            for (int i = 0; i < 2; i++)
                #pragma unroll
                for (int j = 0; j < 4; j++)
                    wmma::mma_sync(facc[i][j], fa[i], fb[j], facc[i][j]);
        }
        __syncthreads();
    }

    // ---- epilogue: optional row scale by dinv, convert fp16, store ----
    #pragma unroll
    for (int i = 0; i < 2; i++) {
        #pragma unroll
        for (int j = 0; j < 4; j++) {
            wmma::store_matrix_sync(&Cs[wid][0][0], facc[i][j], 24, wmma::mem_row_major);
            __syncwarp();
            int r = lane >> 1;
            int gr = block_row + warp_m * 32 + i * 16 + r;
            int col = warp_n * 64 + j * 16 + (lane & 1) * 8;
            if (gr < M) {
                float di = SCALE_D ? g_dinv[gr] : 1.0f;
                float4 v0 = *(float4*)&Cs[wid][r][(lane & 1) * 8];
                float4 v1 = *(float4*)&Cs[wid][r][(lane & 1) * 8 + 4];
                __half2 h0 = __float22half2_rn(make_float2(v0.x * di, v0.y * di));
                __half2 h1 = __float22half2_rn(make_float2(v0.z * di, v0.w * di));
                __half2 h2 = __float22half2_rn(make_float2(v1.x * di, v1.y * di));
                __half2 h3 = __float22half2_rn(make_float2(v1.z * di, v1.w * di));
                uint4 pack;
                pack.x = *reinterpret_cast<unsigned*>(&h0);
                pack.y = *reinterpret_cast<unsigned*>(&h1);
                pack.z = *reinterpret_cast<unsigned*>(&h2);
                pack.w = *reinterpret_cast<unsigned*>(&h3);
                *(uint4*)&Hs[(size_t)gr * BN + col] = pack;
            }
            __syncwarp();
        }
    }
}

// ---------------- launch ------------------------------------------------------
extern "C" void kernel_launch(void* const* d_in, const int* in_sizes, int n_in,
                              void* d_out, int out_size) {
    const float* x  = (const float*)d_in[0];
    const int*   ei = (const int*)d_in[1];
    int base = (n_in >= 9 && in_sizes[2] == 1) ? 3 : 2;
    const float* W1  = (const float*)d_in[base + 0];
    const float* b1  = (const float*)d_in[base + 1];
    const float* Wmu = (const float*)d_in[base + 2];
    const float* bmu = (const float*)d_in[base + 3];
    const float* Wls = (const float*)d_in[base + 4];
    const float* bls = (const float*)d_in[base + 5];
    float* out = (float*)d_out;

    const int N = in_sizes[0] / 256;   // 50000
    const int E = in_sizes[1] / 2;     // 1600000
    const int* src = ei;
    const int* dst = ei + E;

    __half *pHs1, *pHs2, *phh, *pW1h, *pW2h;
    int* pdeg;
    cudaGetSymbolAddress((void**)&pHs1, g_Hs1);
    cudaGetSymbolAddress((void**)&phh,  g_hh);
    cudaGetSymbolAddress((void**)&pHs2, g_Hs2);
    cudaGetSymbolAddress((void**)&pW1h, g_W1h);
    cudaGetSymbolAddress((void**)&pW2h, g_W2h);
    cudaGetSymbolAddress((void**)&pdeg, g_deg);

    // one-time side-stream + events (host resources, not device memory)
    static cudaStream_t s2 = nullptr;
    static cudaEvent_t ev0 = nullptr, ev_scan = nullptr, ev_pre = nullptr;
    if (!s2) {
        cudaStreamCreateWithFlags(&s2, cudaStreamNonBlocking);
        cudaEventCreateWithFlags(&ev0, cudaEventDisableTiming);
        cudaEventCreateWithFlags(&ev_scan, cudaEventDisableTiming);
        cudaEventCreateWithFlags(&ev_pre, cudaEventDisableTiming);
    }

    const int T = 256;
    // ---- fork at t=0: s2 runs weight convert + GEMM1 (graph-independent) ----
    cudaEventRecord(ev0, 0);
    cudaStreamWaitEvent(s2, ev0, 0);
    k_w12h<<<(256 * HID + HID * HID + T - 1) / T, T, 0, s2>>>(W1, Wmu, Wls);
    k_hgemm<false, false><<<(N + 127) / 128, 256, 0, s2>>>(N, 256, x, pW1h, pHs1);

    // ---- main stream: CSR build chain (memset covers scan pad + flags) ----
    cudaMemsetAsync(pdeg, 0, (size_t)(NPAD + 64) * sizeof(int), 0);
    k_hist_rank8<<<(E / 8 + T - 1) / T + 1, T>>>(dst, E);
    k_scan2<<<SCAN_BLOCKS, 1024>>>();
    cudaEventRecord(ev_scan, 0);
    k_scatter8<<<(E / 8 + T - 1) / T + 1, T>>>(src, dst, E);

    // ---- s2: prescale Hs1 by dinv (after GEMM1 + scan), overlaps scatter ----
    cudaStreamWaitEvent(s2, ev_scan, 0);
    k_prescale<<<(N * 32 + T - 1) / T, T, 0, s2>>>(N * 32);
    cudaEventRecord(ev_pre, s2);

    // ---- join, then the serial tail ----
    cudaStreamWaitEvent(0, ev_pre, 0);
    k_agg_relu<<<(N * 32 + T - 1) / T, T>>>(N, b1);
    k_hgemm<true, true><<<(N + 127) / 128, 256>>>(N, 128, phh, pW2h, pHs2);
    k_agg_out<<<(N * 32 + T - 1) / T, T>>>(N, bmu, bls, out);
}